// round 1
// baseline (speedup 1.0000x reference)
#include <cuda_runtime.h>
#include <cstdint>

#define NMAX 100000
#define EMAX 500000
#define D 128

// ---------------- device scratch (no dynamic allocation allowed) ----------------
__device__ int   g_cnt[2][NMAX];          // degree counts (no self loop)
__device__ int   g_rowptr[2][NMAX + 1];   // CSR row pointers
__device__ int   g_cur[2][NMAX];          // build cursors
__device__ int   g_bsum[2][256];          // scan block sums
__device__ float g_dinv[2][NMAX];         // deg^-1/2 (incl self loop)
__device__ int   g_col[2][2 * EMAX];      // CSR adjacency (both directions)
__device__ float g_y[2][NMAX * D];        // x * dinv (aggregation operand)
__device__ float g_t[2][NMAX * D];        // aggregated + scaled = GEMM A operand
__device__ float g_x1[2][NMAX * D];       // layer-1 hidden (residual for layer 2)

// ---------------- small helpers ----------------
__global__ void k_zero_cnt() {
    int i = blockIdx.x * blockDim.x + threadIdx.x;
    if (i < 2 * NMAX) g_cnt[i >= NMAX ? 1 : 0][i >= NMAX ? i - NMAX : i] = 0;
}

__global__ void k_count(const int2* __restrict__ edges, int E, int g) {
    int i = blockIdx.x * blockDim.x + threadIdx.x;
    if (i >= E) return;
    int2 e = edges[i];
    atomicAdd(&g_cnt[g][e.x], 1);
    atomicAdd(&g_cnt[g][e.y], 1);
}

// inclusive scan of counts, phase 1: per-block (1024 elems)
__global__ __launch_bounds__(1024) void k_scan1(int n, int g) {
    __shared__ int sm[1024];
    int tid = threadIdx.x;
    int i = blockIdx.x * 1024 + tid;
    int v = (i < n) ? g_cnt[g][i] : 0;
    sm[tid] = v;
    __syncthreads();
#pragma unroll
    for (int d = 1; d < 1024; d <<= 1) {
        int t = 0;
        if (tid >= d) t = sm[tid - d];
        __syncthreads();
        sm[tid] += t;
        __syncthreads();
    }
    if (i < n) g_rowptr[g][i + 1] = sm[tid];
    if (tid == 1023) g_bsum[g][blockIdx.x] = sm[1023];
}

// phase 2: single block scans the (<=256) block sums
__global__ __launch_bounds__(256) void k_scan2(int nb, int g) {
    __shared__ int sm[256];
    int tid = threadIdx.x;
    int v = (tid < nb) ? g_bsum[g][tid] : 0;
    sm[tid] = v;
    __syncthreads();
#pragma unroll
    for (int d = 1; d < 256; d <<= 1) {
        int t = 0;
        if (tid >= d) t = sm[tid - d];
        __syncthreads();
        sm[tid] += t;
        __syncthreads();
    }
    g_bsum[g][tid] = sm[tid];
}

// phase 3: add block offsets, set cursors, compute dinv
__global__ __launch_bounds__(1024) void k_scan3(int n, int g) {
    int tid = threadIdx.x;
    int i = blockIdx.x * 1024 + tid;
    int off = (blockIdx.x == 0) ? 0 : g_bsum[g][blockIdx.x - 1];
    if (i < n) {
        int v = g_rowptr[g][i + 1] + off;
        g_rowptr[g][i + 1] = v;
        if (i + 1 < n) g_cur[g][i + 1] = v;
        g_dinv[g][i] = rsqrtf((float)(g_cnt[g][i] + 1));
    }
    if (i == 0) {
        g_rowptr[g][0] = 0;
        g_cur[g][0] = 0;
    }
}

__global__ void k_build(const int2* __restrict__ edges, int E, int g) {
    int i = blockIdx.x * blockDim.x + threadIdx.x;
    if (i >= E) return;
    int2 e = edges[i];
    int p1 = atomicAdd(&g_cur[g][e.y], 1);
    g_col[g][p1] = e.x;
    int p2 = atomicAdd(&g_cur[g][e.x], 1);
    g_col[g][p2] = e.y;
}

// y = emb * dinv[row]  (float4 per thread)
__global__ void k_init(const float* __restrict__ emb, int n, int g) {
    int t = blockIdx.x * blockDim.x + threadIdx.x;
    if (t >= n * 32) return;
    int row = t >> 5;
    float di = g_dinv[g][row];
    float4 v = ((const float4*)emb)[t];
    v.x *= di; v.y *= di; v.z *= di; v.w *= di;
    ((float4*)g_y[g])[t] = v;
}

// t[i] = dinv[i] * (y[i] + sum_{j in adj(i)} y[j])   -- warp per node
__global__ void k_agg(int n, int g) {
    int w = (blockIdx.x * blockDim.x + threadIdx.x) >> 5;
    if (w >= n) return;
    int lane = threadIdx.x & 31;
    const float4* __restrict__ y4 = (const float4*)g_y[g];
    float4 acc = y4[w * 32 + lane];  // self loop
    int beg = g_rowptr[g][w];
    int end = g_rowptr[g][w + 1];
    const int* __restrict__ col = g_col[g];
    for (int p = beg; p < end; p++) {
        int j = __ldg(&col[p]);
        float4 v = y4[j * 32 + lane];
        acc.x += v.x; acc.y += v.y; acc.z += v.z; acc.w += v.w;
    }
    float di = g_dinv[g][w];
    acc.x *= di; acc.y *= di; acc.z *= di; acc.w *= di;
    ((float4*)g_t[g])[w * 32 + lane] = acc;
}

// out = relu(T @ W + resid); optionally also write y_next = out * dinv.
// BM=64 rows per block, full K=128 in shared memory. 256 threads, 4x8 microtile.
#define AS_PITCH 68
template <bool WRITE_Y>
__global__ __launch_bounds__(256, 2) void k_gemm(int g, const float* __restrict__ W,
                                                 const float* __restrict__ resid_ext,
                                                 float* __restrict__ out_ext, int n) {
    extern __shared__ float sm[];
    float* Bs = sm;               // [128][128]
    float* As = sm + D * D;       // [128][AS_PITCH]
    const float* __restrict__ T = g_t[g];
    const float* __restrict__ resid = resid_ext ? resid_ext : g_x1[g];
    float* __restrict__ out = out_ext ? out_ext : g_x1[g];

    int tid = threadIdx.x;
    int bm = blockIdx.x * 64;

    // load W (16384 floats) into Bs
    {
        const float4* W4 = (const float4*)W;
        float4* Bs4 = (float4*)Bs;
#pragma unroll
        for (int i = 0; i < 16; i++) Bs4[tid + 256 * i] = W4[tid + 256 * i];
    }
    // load A tile (64 rows x 128 cols) transposed into As[k][m]
#pragma unroll
    for (int i = 0; i < 32; i++) {
        int e = tid + 256 * i;
        int m = e >> 7;
        int k = e & 127;
        int row = bm + m;
        if (row >= n) row = n - 1;
        As[k * AS_PITCH + m] = T[row * D + k];
    }
    __syncthreads();

    int tx = tid & 15;   // 16 col groups * 8 cols
    int ty = tid >> 4;   // 16 row groups * 4 rows
    float acc[4][8];
#pragma unroll
    for (int r = 0; r < 4; r++)
#pragma unroll
        for (int j = 0; j < 8; j++) acc[r][j] = 0.f;

#pragma unroll 8
    for (int k = 0; k < D; k++) {
        float4 a = *(const float4*)&As[k * AS_PITCH + ty * 4];
        float4 b0 = *(const float4*)&Bs[k * D + tx * 8];
        float4 b1 = *(const float4*)&Bs[k * D + tx * 8 + 4];
        float av[4] = {a.x, a.y, a.z, a.w};
        float bv[8] = {b0.x, b0.y, b0.z, b0.w, b1.x, b1.y, b1.z, b1.w};
#pragma unroll
        for (int r = 0; r < 4; r++)
#pragma unroll
            for (int j = 0; j < 8; j++) acc[r][j] = fmaf(av[r], bv[j], acc[r][j]);
    }

#pragma unroll
    for (int r = 0; r < 4; r++) {
        int row = bm + ty * 4 + r;
        if (row < n) {
            const float4* rs = (const float4*)&resid[row * D + tx * 8];
            float4 r0 = rs[0], r1 = rs[1];
            float v[8];
            v[0] = acc[r][0] + r0.x; v[1] = acc[r][1] + r0.y;
            v[2] = acc[r][2] + r0.z; v[3] = acc[r][3] + r0.w;
            v[4] = acc[r][4] + r1.x; v[5] = acc[r][5] + r1.y;
            v[6] = acc[r][6] + r1.z; v[7] = acc[r][7] + r1.w;
#pragma unroll
            for (int j = 0; j < 8; j++) v[j] = fmaxf(v[j], 0.f);
            float4 o0 = make_float4(v[0], v[1], v[2], v[3]);
            float4 o1 = make_float4(v[4], v[5], v[6], v[7]);
            float4* op = (float4*)&out[row * D + tx * 8];
            op[0] = o0;
            op[1] = o1;
            if (WRITE_Y) {
                float di = g_dinv[g][row];
                float4 y0 = make_float4(v[0] * di, v[1] * di, v[2] * di, v[3] * di);
                float4 y1 = make_float4(v[4] * di, v[5] * di, v[6] * di, v[7] * di);
                float4* yp = (float4*)&g_y[g][row * D + tx * 8];
                yp[0] = y0;
                yp[1] = y1;
            }
        }
    }
}

// gather seed rows from the already-written ent_hid regions of d_out
__global__ void k_seed(const int* __restrict__ s0, const int* __restrict__ s1,
                       const float* __restrict__ ent0, const float* __restrict__ ent1,
                       float* __restrict__ o0, float* __restrict__ o1, int nseed) {
    int w = (blockIdx.x * blockDim.x + threadIdx.x) >> 5;
    if (w >= 2 * nseed) return;
    int lane = threadIdx.x & 31;
    int which = (w >= nseed) ? 1 : 0;
    int k = w - which * nseed;
    const int* s = which ? s1 : s0;
    const float4* ent = (const float4*)(which ? ent1 : ent0);
    float4* o = (float4*)(which ? o1 : o0);
    int r = s[k];
    o[k * 32 + lane] = ent[r * 32 + lane];
}

// ---------------- host launcher ----------------
extern "C" void kernel_launch(void* const* d_in, const int* in_sizes, int n_in,
                              void* d_out, int out_size) {
    const int n = in_sizes[4] / D;      // 100000
    const int E = in_sizes[6] / 2;      // 500000
    const int nseed = in_sizes[0];      // 10000

    const int* seeds[2] = {(const int*)d_in[0], (const int*)d_in[1]};
    const float* emb[2] = {(const float*)d_in[4], (const float*)d_in[5]};
    const int2* edges[2] = {(const int2*)d_in[6], (const int2*)d_in[7]};
    const float* W1 = (const float*)d_in[8];
    const float* W2 = (const float*)d_in[9];

    float* out = (float*)d_out;
    float* out_seed[2] = {out, out + (size_t)nseed * D};
    float* out_ent[2] = {out + (size_t)2 * nseed * D,
                         out + (size_t)2 * nseed * D + (size_t)n * D};

    const int smem_gemm = (D * D + D * AS_PITCH) * (int)sizeof(float);
    cudaFuncSetAttribute(k_gemm<true>, cudaFuncAttributeMaxDynamicSharedMemorySize, smem_gemm);
    cudaFuncSetAttribute(k_gemm<false>, cudaFuncAttributeMaxDynamicSharedMemorySize, smem_gemm);

    const int nb_scan = (n + 1023) / 1024;

    k_zero_cnt<<<(2 * NMAX + 255) / 256, 256>>>();
    for (int g = 0; g < 2; g++) {
        k_count<<<(E + 255) / 256, 256>>>(edges[g], E, g);
        k_scan1<<<nb_scan, 1024>>>(n, g);
        k_scan2<<<1, 256>>>(nb_scan, g);
        k_scan3<<<nb_scan, 1024>>>(n, g);
        k_build<<<(E + 255) / 256, 256>>>(edges[g], E, g);
        k_init<<<(n * 32 + 255) / 256, 256>>>(emb[g], n, g);
    }
    const int agg_grid = (n * 32 + 255) / 256;
    const int gemm_grid = (n + 63) / 64;
    for (int g = 0; g < 2; g++) {
        // layer 1: resid = emb, out = g_x1, write y for next layer
        k_agg<<<agg_grid, 256>>>(n, g);
        k_gemm<true><<<gemm_grid, 256, smem_gemm>>>(g, W1, emb[g], nullptr, n);
        // layer 2: resid = g_x1, out = d_out ent region
        k_agg<<<agg_grid, 256>>>(n, g);
        k_gemm<false><<<gemm_grid, 256, smem_gemm>>>(g, W2, nullptr, out_ent[g], n);
    }
    k_seed<<<(2 * nseed * 32 + 255) / 256, 256>>>(seeds[0], seeds[1], out_ent[0], out_ent[1],
                                                  out_seed[0], out_seed[1], nseed);
}

// round 2
// speedup vs baseline: 1.1003x; 1.1003x over previous
#include <cuda_runtime.h>
#include <cstdint>

#define NMAX 100000
#define EMAX 500000
#define D 128

// ---------------- device scratch (no dynamic allocation allowed) ----------------
__device__ int   g_cnt[2][NMAX];          // degree counts (no self loop)
__device__ int   g_rowptr[2][NMAX + 1];   // CSR row pointers
__device__ int   g_cur[2][NMAX];          // build cursors
__device__ int   g_bsum[2][256];          // scan block sums
__device__ float g_dinv[2][NMAX];         // deg^-1/2 (incl self loop)
__device__ int   g_col[2][2 * EMAX];      // CSR adjacency (both directions)
__device__ float g_y[2][NMAX * D];        // x * dinv (aggregation operand)
__device__ float g_t[2][NMAX * D];        // aggregated + scaled = GEMM A operand
__device__ float g_x1[2][NMAX * D];       // layer-1 hidden (residual for layer 2)

// ---------------- small helpers ----------------
__global__ void k_zero_cnt(int n, int g) {
    int i = blockIdx.x * blockDim.x + threadIdx.x;
    if (i < n) g_cnt[g][i] = 0;
}

__global__ void k_count(const int2* __restrict__ edges, int E, int g) {
    int i = blockIdx.x * blockDim.x + threadIdx.x;
    if (i >= E) return;
    int2 e = edges[i];
    atomicAdd(&g_cnt[g][e.x], 1);
    atomicAdd(&g_cnt[g][e.y], 1);
}

// inclusive scan of counts, phase 1: per-block (1024 elems)
__global__ __launch_bounds__(1024) void k_scan1(int n, int g) {
    __shared__ int sm[1024];
    int tid = threadIdx.x;
    int i = blockIdx.x * 1024 + tid;
    int v = (i < n) ? g_cnt[g][i] : 0;
    sm[tid] = v;
    __syncthreads();
#pragma unroll
    for (int d = 1; d < 1024; d <<= 1) {
        int t = 0;
        if (tid >= d) t = sm[tid - d];
        __syncthreads();
        sm[tid] += t;
        __syncthreads();
    }
    if (i < n) g_rowptr[g][i + 1] = sm[tid];
    if (tid == 1023) g_bsum[g][blockIdx.x] = sm[1023];
}

// phase 2: single block scans the (<=256) block sums
__global__ __launch_bounds__(256) void k_scan2(int nb, int g) {
    __shared__ int sm[256];
    int tid = threadIdx.x;
    int v = (tid < nb) ? g_bsum[g][tid] : 0;
    sm[tid] = v;
    __syncthreads();
#pragma unroll
    for (int d = 1; d < 256; d <<= 1) {
        int t = 0;
        if (tid >= d) t = sm[tid - d];
        __syncthreads();
        sm[tid] += t;
        __syncthreads();
    }
    g_bsum[g][tid] = sm[tid];
}

// phase 3: add block offsets, set cursors, compute dinv
__global__ __launch_bounds__(1024) void k_scan3(int n, int g) {
    int tid = threadIdx.x;
    int i = blockIdx.x * 1024 + tid;
    int off = (blockIdx.x == 0) ? 0 : g_bsum[g][blockIdx.x - 1];
    if (i < n) {
        int v = g_rowptr[g][i + 1] + off;
        g_rowptr[g][i + 1] = v;
        if (i + 1 < n) g_cur[g][i + 1] = v;
        g_dinv[g][i] = rsqrtf((float)(g_cnt[g][i] + 1));
    }
    if (i == 0) {
        g_rowptr[g][0] = 0;
        g_cur[g][0] = 0;
    }
}

__global__ void k_build(const int2* __restrict__ edges, int E, int g) {
    int i = blockIdx.x * blockDim.x + threadIdx.x;
    if (i >= E) return;
    int2 e = edges[i];
    int p1 = atomicAdd(&g_cur[g][e.y], 1);
    g_col[g][p1] = e.x;
    int p2 = atomicAdd(&g_cur[g][e.x], 1);
    g_col[g][p2] = e.y;
}

// y = emb * dinv[row]  (float4 per thread)
__global__ void k_init(const float* __restrict__ emb, int n, int g) {
    int t = blockIdx.x * blockDim.x + threadIdx.x;
    if (t >= n * 32) return;
    int row = t >> 5;
    float di = g_dinv[g][row];
    float4 v = ((const float4*)emb)[t];
    v.x *= di; v.y *= di; v.z *= di; v.w *= di;
    ((float4*)g_y[g])[t] = v;
}

// t[i] = dinv[i] * (y[i] + sum_{j in adj(i)} y[j])   -- warp per node
__global__ void k_agg(int n, int g) {
    int w = (blockIdx.x * blockDim.x + threadIdx.x) >> 5;
    if (w >= n) return;
    int lane = threadIdx.x & 31;
    const float4* __restrict__ y4 = (const float4*)g_y[g];
    float4 acc = y4[w * 32 + lane];  // self loop
    int beg = g_rowptr[g][w];
    int end = g_rowptr[g][w + 1];
    const int* __restrict__ col = g_col[g];
    int p = beg;
    // 4-wide software pipeline: independent loads, then adds
    for (; p + 4 <= end; p += 4) {
        int j0 = __ldg(&col[p]);
        int j1 = __ldg(&col[p + 1]);
        int j2 = __ldg(&col[p + 2]);
        int j3 = __ldg(&col[p + 3]);
        float4 v0 = y4[j0 * 32 + lane];
        float4 v1 = y4[j1 * 32 + lane];
        float4 v2 = y4[j2 * 32 + lane];
        float4 v3 = y4[j3 * 32 + lane];
        acc.x += v0.x; acc.y += v0.y; acc.z += v0.z; acc.w += v0.w;
        acc.x += v1.x; acc.y += v1.y; acc.z += v1.z; acc.w += v1.w;
        acc.x += v2.x; acc.y += v2.y; acc.z += v2.z; acc.w += v2.w;
        acc.x += v3.x; acc.y += v3.y; acc.z += v3.z; acc.w += v3.w;
    }
    for (; p < end; p++) {
        int j = __ldg(&col[p]);
        float4 v = y4[j * 32 + lane];
        acc.x += v.x; acc.y += v.y; acc.z += v.z; acc.w += v.w;
    }
    float di = g_dinv[g][w];
    acc.x *= di; acc.y *= di; acc.z *= di; acc.w *= di;
    ((float4*)g_t[g])[w * 32 + lane] = acc;
}

// packed f32x2 FMA (FFMA2) -- only reachable via PTX on sm_103a
#define FFMA2(d, a, b) \
    asm("fma.rn.f32x2 %0, %1, %2, %0;" : "+l"(d) : "l"(a), "l"(b))
#define PACK_DUP(d, s) \
    asm("mov.b64 %0, {%1, %1};" : "=l"(d) : "f"(s))
#define UNPACK2(lo, hi, s) \
    asm("mov.b64 {%0, %1}, %2;" : "=f"(lo), "=f"(hi) : "l"(s))

// out = relu(T @ W + resid); optionally also write y_next = out * dinv.
// BM=64 rows per block, full K=128 in shared memory. 256 threads, 4x8 microtile
// computed as 4 rows x 4 packed column-pairs via fma.rn.f32x2.
#define AS_PITCH 68
template <bool WRITE_Y>
__global__ __launch_bounds__(256, 2) void k_gemm(int g, const float* __restrict__ W,
                                                 const float* __restrict__ resid_ext,
                                                 float* __restrict__ out_ext, int n) {
    extern __shared__ float sm[];
    float* Bs = sm;               // [128][128]
    float* As = sm + D * D;       // [128][AS_PITCH]
    const float* __restrict__ T = g_t[g];
    const float* __restrict__ resid = resid_ext ? resid_ext : g_x1[g];
    float* __restrict__ out = out_ext ? out_ext : g_x1[g];

    int tid = threadIdx.x;
    int bm = blockIdx.x * 64;

    // load W (16384 floats) into Bs
    {
        const float4* W4 = (const float4*)W;
        float4* Bs4 = (float4*)Bs;
#pragma unroll
        for (int i = 0; i < 16; i++) Bs4[tid + 256 * i] = W4[tid + 256 * i];
    }
    // load A tile (64 rows x 128 cols) transposed into As[k][m]
#pragma unroll
    for (int i = 0; i < 32; i++) {
        int e = tid + 256 * i;
        int m = e >> 7;
        int k = e & 127;
        int row = bm + m;
        if (row >= n) row = n - 1;
        As[k * AS_PITCH + m] = T[row * D + k];
    }
    __syncthreads();

    int tx = tid & 15;   // 16 col groups * 8 cols (4 packed pairs)
    int ty = tid >> 4;   // 16 row groups * 4 rows
    unsigned long long acc2[4][4];
#pragma unroll
    for (int r = 0; r < 4; r++)
#pragma unroll
        for (int p = 0; p < 4; p++) acc2[r][p] = 0ull;

#pragma unroll 8
    for (int k = 0; k < D; k++) {
        float4 a = *(const float4*)&As[k * AS_PITCH + ty * 4];
        const unsigned long long* b8 =
            (const unsigned long long*)&Bs[k * D + tx * 8];
        unsigned long long b0 = b8[0], b1 = b8[1], b2 = b8[2], b3 = b8[3];
        float av[4] = {a.x, a.y, a.z, a.w};
#pragma unroll
        for (int r = 0; r < 4; r++) {
            unsigned long long ap;
            PACK_DUP(ap, av[r]);
            FFMA2(acc2[r][0], ap, b0);
            FFMA2(acc2[r][1], ap, b1);
            FFMA2(acc2[r][2], ap, b2);
            FFMA2(acc2[r][3], ap, b3);
        }
    }

#pragma unroll
    for (int r = 0; r < 4; r++) {
        int row = bm + ty * 4 + r;
        if (row < n) {
            const float4* rs = (const float4*)&resid[row * D + tx * 8];
            float4 r0 = rs[0], r1 = rs[1];
            float v[8];
            UNPACK2(v[0], v[1], acc2[r][0]);
            UNPACK2(v[2], v[3], acc2[r][1]);
            UNPACK2(v[4], v[5], acc2[r][2]);
            UNPACK2(v[6], v[7], acc2[r][3]);
            v[0] += r0.x; v[1] += r0.y; v[2] += r0.z; v[3] += r0.w;
            v[4] += r1.x; v[5] += r1.y; v[6] += r1.z; v[7] += r1.w;
#pragma unroll
            for (int j = 0; j < 8; j++) v[j] = fmaxf(v[j], 0.f);
            float4 o0 = make_float4(v[0], v[1], v[2], v[3]);
            float4 o1 = make_float4(v[4], v[5], v[6], v[7]);
            float4* op = (float4*)&out[row * D + tx * 8];
            op[0] = o0;
            op[1] = o1;
            if (WRITE_Y) {
                float di = g_dinv[g][row];
                float4 y0 = make_float4(v[0] * di, v[1] * di, v[2] * di, v[3] * di);
                float4 y1 = make_float4(v[4] * di, v[5] * di, v[6] * di, v[7] * di);
                float4* yp = (float4*)&g_y[g][row * D + tx * 8];
                yp[0] = y0;
                yp[1] = y1;
            }
        }
    }
}

// gather seed rows from the already-written ent_hid regions of d_out
__global__ void k_seed(const int* __restrict__ s0, const int* __restrict__ s1,
                       const float* __restrict__ ent0, const float* __restrict__ ent1,
                       float* __restrict__ o0, float* __restrict__ o1, int nseed) {
    int w = (blockIdx.x * blockDim.x + threadIdx.x) >> 5;
    if (w >= 2 * nseed) return;
    int lane = threadIdx.x & 31;
    int which = (w >= nseed) ? 1 : 0;
    int k = w - which * nseed;
    const int* s = which ? s1 : s0;
    const float4* ent = (const float4*)(which ? ent1 : ent0);
    float4* o = (float4*)(which ? o1 : o0);
    int r = s[k];
    o[k * 32 + lane] = ent[r * 32 + lane];
}

// ---------------- host launcher ----------------
extern "C" void kernel_launch(void* const* d_in, const int* in_sizes, int n_in,
                              void* d_out, int out_size) {
    const int n = in_sizes[4] / D;      // 100000
    const int E = in_sizes[6] / 2;      // 500000
    const int nseed = in_sizes[0];      // 10000

    const int* seeds[2] = {(const int*)d_in[0], (const int*)d_in[1]};
    const float* emb[2] = {(const float*)d_in[4], (const float*)d_in[5]};
    const int2* edges[2] = {(const int2*)d_in[6], (const int2*)d_in[7]};
    const float* W1 = (const float*)d_in[8];
    const float* W2 = (const float*)d_in[9];

    float* out = (float*)d_out;
    float* out_seed[2] = {out, out + (size_t)nseed * D};
    float* out_ent[2] = {out + (size_t)2 * nseed * D,
                         out + (size_t)2 * nseed * D + (size_t)n * D};

    const int smem_gemm = (D * D + D * AS_PITCH) * (int)sizeof(float);

    // one-time resources (no device memory involved)
    static cudaStream_t s_aux = [] {
        cudaStream_t s;
        cudaStreamCreateWithFlags(&s, cudaStreamNonBlocking);
        return s;
    }();
    static cudaEvent_t ev_fork = [] {
        cudaEvent_t e;
        cudaEventCreateWithFlags(&e, cudaEventDisableTiming);
        return e;
    }();
    static cudaEvent_t ev_join = [] {
        cudaEvent_t e;
        cudaEventCreateWithFlags(&e, cudaEventDisableTiming);
        return e;
    }();
    static bool attr_done = [] {
        cudaFuncSetAttribute(k_gemm<true>, cudaFuncAttributeMaxDynamicSharedMemorySize,
                             (D * D + D * AS_PITCH) * (int)sizeof(float));
        cudaFuncSetAttribute(k_gemm<false>, cudaFuncAttributeMaxDynamicSharedMemorySize,
                             (D * D + D * AS_PITCH) * (int)sizeof(float));
        return true;
    }();
    (void)attr_done;

    const int nb_scan = (n + 1023) / 1024;
    const int agg_grid = (n * 32 + 255) / 256;
    const int gemm_grid = (n + 63) / 64;

    // fork: aux stream joins the captured (legacy) stream
    cudaEventRecord(ev_fork, 0);
    cudaStreamWaitEvent(s_aux, ev_fork, 0);

    cudaStream_t strm[2] = {0, s_aux};
    for (int g = 0; g < 2; g++) {
        cudaStream_t s = strm[g];
        k_zero_cnt<<<(n + 255) / 256, 256, 0, s>>>(n, g);
        k_count<<<(E + 255) / 256, 256, 0, s>>>(edges[g], E, g);
        k_scan1<<<nb_scan, 1024, 0, s>>>(n, g);
        k_scan2<<<1, 256, 0, s>>>(nb_scan, g);
        k_scan3<<<nb_scan, 1024, 0, s>>>(n, g);
        k_build<<<(E + 255) / 256, 256, 0, s>>>(edges[g], E, g);
        k_init<<<(n * 32 + 255) / 256, 256, 0, s>>>(emb[g], n, g);
        // layer 1: resid = emb, out = g_x1, write y for next layer
        k_agg<<<agg_grid, 256, 0, s>>>(n, g);
        k_gemm<true><<<gemm_grid, 256, smem_gemm, s>>>(g, W1, emb[g], nullptr, n);
        // layer 2: resid = g_x1, out = d_out ent region
        k_agg<<<agg_grid, 256, 0, s>>>(n, g);
        k_gemm<false><<<gemm_grid, 256, smem_gemm, s>>>(g, W2, nullptr, out_ent[g], n);
    }

    // join: seed gather depends on both pipelines
    cudaEventRecord(ev_join, s_aux);
    cudaStreamWaitEvent(0, ev_join, 0);
    k_seed<<<(2 * nseed * 32 + 255) / 256, 256>>>(seeds[0], seeds[1], out_ent[0], out_ent[1],
                                                  out_seed[0], out_seed[1], nseed);
}

// round 4
// speedup vs baseline: 1.7674x; 1.6063x over previous
#include <cuda_runtime.h>
#include <cuda_bf16.h>
#include <cstdint>

#define NMAX 100000
#define EMAX 500000
#define D 128

// ---------------- device scratch ----------------
__device__ int   g_cnt[2][NMAX];
__device__ int   g_rowptr[2][NMAX + 1];
__device__ int   g_cur[2][NMAX];
__device__ int   g_bsum[2][256];
__device__ float g_dinv[2][NMAX];
__device__ int   g_col[2][2 * EMAX];
__device__ float g_y[2][NMAX * D];      // x * dinv (aggregation operand)
__device__ uint4 g_tp[2][NMAX * 32];    // aggregated, packed bf16 (hi<<16|lo) x4
__device__ float g_x1[2][NMAX * D];     // layer-1 hidden (residual for layer 2)
__device__ uint4 g_wh4[2][2048];        // W hi bf16 [k][n] (128x128, 16 uint4/row)
__device__ uint4 g_wl4[2][2048];        // W lo bf16 [k][n]

// ---------------- setup kernels ----------------
__global__ void k_zero_cnt(int n, int g) {
    int i = blockIdx.x * blockDim.x + threadIdx.x;
    if (i < n) g_cnt[g][i] = 0;
}

__global__ void k_count(const int2* __restrict__ edges, int E, int g) {
    int i = blockIdx.x * blockDim.x + threadIdx.x;
    if (i >= E) return;
    int2 e = edges[i];
    atomicAdd(&g_cnt[g][e.x], 1);
    atomicAdd(&g_cnt[g][e.y], 1);
}

__global__ __launch_bounds__(1024) void k_scan1(int n, int g) {
    __shared__ int sm[1024];
    int tid = threadIdx.x;
    int i = blockIdx.x * 1024 + tid;
    int v = (i < n) ? g_cnt[g][i] : 0;
    sm[tid] = v;
    __syncthreads();
#pragma unroll
    for (int d = 1; d < 1024; d <<= 1) {
        int t = 0;
        if (tid >= d) t = sm[tid - d];
        __syncthreads();
        sm[tid] += t;
        __syncthreads();
    }
    if (i < n) g_rowptr[g][i + 1] = sm[tid];
    if (tid == 1023) g_bsum[g][blockIdx.x] = sm[1023];
}

__global__ __launch_bounds__(256) void k_scan2(int nb, int g) {
    __shared__ int sm[256];
    int tid = threadIdx.x;
    int v = (tid < nb) ? g_bsum[g][tid] : 0;
    sm[tid] = v;
    __syncthreads();
#pragma unroll
    for (int d = 1; d < 256; d <<= 1) {
        int t = 0;
        if (tid >= d) t = sm[tid - d];
        __syncthreads();
        sm[tid] += t;
        __syncthreads();
    }
    g_bsum[g][tid] = sm[tid];
}

__global__ __launch_bounds__(1024) void k_scan3(int n, int g) {
    int tid = threadIdx.x;
    int i = blockIdx.x * 1024 + tid;
    int off = (blockIdx.x == 0) ? 0 : g_bsum[g][blockIdx.x - 1];
    if (i < n) {
        int v = g_rowptr[g][i + 1] + off;
        g_rowptr[g][i + 1] = v;
        if (i + 1 < n) g_cur[g][i + 1] = v;
        g_dinv[g][i] = rsqrtf((float)(g_cnt[g][i] + 1));
    }
    if (i == 0) {
        g_rowptr[g][0] = 0;
        g_cur[g][0] = 0;
    }
}

__global__ void k_build(const int2* __restrict__ edges, int E, int g) {
    int i = blockIdx.x * blockDim.x + threadIdx.x;
    if (i >= E) return;
    int2 e = edges[i];
    int p1 = atomicAdd(&g_cur[g][e.y], 1);
    g_col[g][p1] = e.x;
    int p2 = atomicAdd(&g_cur[g][e.x], 1);
    g_col[g][p2] = e.y;
}

__global__ void k_init(const float* __restrict__ emb, int n, int g) {
    int t = blockIdx.x * blockDim.x + threadIdx.x;
    if (t >= n * 32) return;
    int row = t >> 5;
    float di = g_dinv[g][row];
    float4 v = ((const float4*)emb)[t];
    v.x *= di; v.y *= di; v.z *= di; v.w *= di;
    ((float4*)g_y[g])[t] = v;
}

// split W[k][n] -> bf16 hi/lo (row-major [k][n], B-operand-ready)
__global__ void k_prepw(const float* __restrict__ W, int widx) {
    int e = blockIdx.x * blockDim.x + threadIdx.x;
    if (e >= D * D) return;
    float v = W[e];
    __nv_bfloat16 h = __float2bfloat16(v);
    float hf = __bfloat162float(h);
    __nv_bfloat16 l = __float2bfloat16(v - hf);
    ((unsigned short*)g_wh4[widx])[e] = __bfloat16_as_ushort(h);
    ((unsigned short*)g_wl4[widx])[e] = __bfloat16_as_ushort(l);
}

__device__ __forceinline__ uint32_t pack_hilo(float a) {
    __nv_bfloat16 h = __float2bfloat16(a);
    float hf = __bfloat162float(h);
    __nv_bfloat16 l = __float2bfloat16(a - hf);
    return ((uint32_t)__bfloat16_as_ushort(h) << 16) | (uint32_t)__bfloat16_as_ushort(l);
}

// t[i] = dinv[i]*(y[i] + sum_nbr y[j]); pack as bf16 hi/lo u32
__global__ void k_agg(int n, int g) {
    int w = (blockIdx.x * blockDim.x + threadIdx.x) >> 5;
    if (w >= n) return;
    int lane = threadIdx.x & 31;
    const float4* __restrict__ y4 = (const float4*)g_y[g];
    float4 acc = y4[w * 32 + lane];
    int beg = g_rowptr[g][w];
    int end = g_rowptr[g][w + 1];
    const int* __restrict__ col = g_col[g];
    int p = beg;
    for (; p + 4 <= end; p += 4) {
        int j0 = __ldg(&col[p]);
        int j1 = __ldg(&col[p + 1]);
        int j2 = __ldg(&col[p + 2]);
        int j3 = __ldg(&col[p + 3]);
        float4 v0 = y4[j0 * 32 + lane];
        float4 v1 = y4[j1 * 32 + lane];
        float4 v2 = y4[j2 * 32 + lane];
        float4 v3 = y4[j3 * 32 + lane];
        acc.x += v0.x; acc.y += v0.y; acc.z += v0.z; acc.w += v0.w;
        acc.x += v1.x; acc.y += v1.y; acc.z += v1.z; acc.w += v1.w;
        acc.x += v2.x; acc.y += v2.y; acc.z += v2.z; acc.w += v2.w;
        acc.x += v3.x; acc.y += v3.y; acc.z += v3.z; acc.w += v3.w;
    }
    for (; p < end; p++) {
        int j = __ldg(&col[p]);
        float4 v = y4[j * 32 + lane];
        acc.x += v.x; acc.y += v.y; acc.z += v.z; acc.w += v.w;
    }
    float di = g_dinv[g][w];
    uint4 pk;
    pk.x = pack_hilo(acc.x * di);
    pk.y = pack_hilo(acc.y * di);
    pk.z = pack_hilo(acc.z * di);
    pk.w = pack_hilo(acc.w * di);
    g_tp[g][w * 32 + lane] = pk;
}

// ---------------- split-bf16 mma.sync GEMM: out = relu(T@W + resid) ----------------
#define PITCH 272          // 256B data + 16B pad per 128-col bf16 row
#define MAT_BYTES (128 * PITCH)
#define SMEM_HG (4 * MAT_BYTES)

__device__ __forceinline__ uint32_t smem_u32(const void* p) {
    uint32_t a;
    asm("{ .reg .u64 t; cvta.to.shared.u64 t, %1; cvt.u32.u64 %0, t; }"
        : "=r"(a) : "l"(p));
    return a;
}
#define LDSM_X4(r0, r1, r2, r3, addr) \
    asm volatile("ldmatrix.sync.aligned.m8n8.x4.shared.b16 {%0,%1,%2,%3}, [%4];" \
                 : "=r"(r0), "=r"(r1), "=r"(r2), "=r"(r3) : "r"(addr))
#define LDSM_X4_T(r0, r1, r2, r3, addr) \
    asm volatile("ldmatrix.sync.aligned.m8n8.x4.trans.shared.b16 {%0,%1,%2,%3}, [%4];" \
                 : "=r"(r0), "=r"(r1), "=r"(r2), "=r"(r3) : "r"(addr))
#define MMA_BF16(c0, c1, c2, c3, a0, a1, a2, a3, b0, b1) \
    asm volatile("mma.sync.aligned.m16n8k16.row.col.f32.bf16.bf16.f32 " \
                 "{%0,%1,%2,%3}, {%4,%5,%6,%7}, {%8,%9}, {%0,%1,%2,%3};" \
                 : "+f"(c0), "+f"(c1), "+f"(c2), "+f"(c3) \
                 : "r"(a0), "r"(a1), "r"(a2), "r"(a3), "r"(b0), "r"(b1))

template <bool WRITE_Y>
__global__ __launch_bounds__(256, 1) void k_hgemm(int g, int widx,
                                                  const float* __restrict__ resid_ext,
                                                  float* __restrict__ out_ext, int n) {
    extern __shared__ char smch[];
    char* Ah = smch;
    char* Al = smch + MAT_BYTES;
    char* Wh = smch + 2 * MAT_BYTES;
    char* Wl = smch + 3 * MAT_BYTES;
    const float* __restrict__ resid = resid_ext ? resid_ext : g_x1[g];
    float* __restrict__ out = out_ext ? out_ext : g_x1[g];

    int tid = threadIdx.x;
    int lane = tid & 31;
    int w = tid >> 5;
    int bm = blockIdx.x * 128;

    // load W hi/lo (128 rows x 16 uint4) into pitched SMEM
    {
        const uint4* wh = g_wh4[widx];
        const uint4* wl = g_wl4[widx];
#pragma unroll
        for (int i = 0; i < 8; i++) {
            int e = tid + i * 256;
            int r = e >> 4, c = e & 15;
            *(uint4*)(Wh + r * PITCH + c * 16) = wh[e];
            *(uint4*)(Wl + r * PITCH + c * 16) = wl[e];
        }
    }
    // load packed A tile, split into hi/lo SMEM
    {
        const uint4* ap = g_tp[g];
#pragma unroll
        for (int i = 0; i < 16; i++) {
            int e = tid + i * 256;
            int r = e >> 5, c = e & 31;
            int row = bm + r;
            if (row >= n) row = n - 1;
            uint4 v = ap[(size_t)row * 32 + c];
            ushort4 hv, lv;
            hv.x = (unsigned short)(v.x >> 16); lv.x = (unsigned short)(v.x & 0xffff);
            hv.y = (unsigned short)(v.y >> 16); lv.y = (unsigned short)(v.y & 0xffff);
            hv.z = (unsigned short)(v.z >> 16); lv.z = (unsigned short)(v.z & 0xffff);
            hv.w = (unsigned short)(v.w >> 16); lv.w = (unsigned short)(v.w & 0xffff);
            *(ushort4*)(Ah + r * PITCH + c * 8) = hv;
            *(ushort4*)(Al + r * PITCH + c * 8) = lv;
        }
    }
    __syncthreads();

    // ldmatrix lane addresses
    uint32_t sAh = smem_u32(Ah), sAl = smem_u32(Al);
    uint32_t sWh = smem_u32(Wh), sWl = smem_u32(Wl);
    int arow = w * 16 + (lane & 15);
    uint32_t aoff_h = sAh + (uint32_t)arow * PITCH + (uint32_t)(lane >> 4) * 16;
    uint32_t aoff_l = sAl + (uint32_t)arow * PITCH + (uint32_t)(lane >> 4) * 16;
    uint32_t boff_h = sWh + (uint32_t)(lane & 15) * PITCH + (uint32_t)(lane >> 4) * 16;
    uint32_t boff_l = sWl + (uint32_t)(lane & 15) * PITCH + (uint32_t)(lane >> 4) * 16;

    float acc[16][4];
#pragma unroll
    for (int i = 0; i < 16; i++)
#pragma unroll
        for (int j = 0; j < 4; j++) acc[i][j] = 0.f;

#pragma unroll 1
    for (int pass = 0; pass < 3; pass++) {
        uint32_t aoff = (pass == 2) ? aoff_l : aoff_h;
        uint32_t boff = (pass == 1) ? boff_l : boff_h;
#pragma unroll
        for (int k = 0; k < 8; k++) {
            uint32_t a0, a1, a2, a3;
            LDSM_X4(a0, a1, a2, a3, aoff + (uint32_t)k * 32);
#pragma unroll
            for (int nt2 = 0; nt2 < 8; nt2++) {
                uint32_t b0, b1, b2, b3;
                LDSM_X4_T(b0, b1, b2, b3, boff + (uint32_t)k * (16 * PITCH) + (uint32_t)nt2 * 32);
                MMA_BF16(acc[2 * nt2][0], acc[2 * nt2][1], acc[2 * nt2][2], acc[2 * nt2][3],
                         a0, a1, a2, a3, b0, b1);
                MMA_BF16(acc[2 * nt2 + 1][0], acc[2 * nt2 + 1][1], acc[2 * nt2 + 1][2], acc[2 * nt2 + 1][3],
                         a0, a1, a2, a3, b2, b3);
            }
        }
    }

    // epilogue: relu(acc + resid), optional y = out * dinv
    int r0 = bm + w * 16 + (lane >> 2);
    int r1 = r0 + 8;
    int cbase = (lane & 3) * 2;
    bool v0 = r0 < n, v1 = r1 < n;
    float di0 = 0.f, di1 = 0.f;
    if (WRITE_Y) {
        if (v0) di0 = g_dinv[g][r0];
        if (v1) di1 = g_dinv[g][r1];
    }
#pragma unroll
    for (int nt = 0; nt < 16; nt++) {
        int col = nt * 8 + cbase;
        if (v0) {
            float2 rv = *(const float2*)&resid[(size_t)r0 * D + col];
            float2 o;
            o.x = fmaxf(acc[nt][0] + rv.x, 0.f);
            o.y = fmaxf(acc[nt][1] + rv.y, 0.f);
            *(float2*)&out[(size_t)r0 * D + col] = o;
            if (WRITE_Y) {
                float2 yv = make_float2(o.x * di0, o.y * di0);
                *(float2*)&g_y[g][(size_t)r0 * D + col] = yv;
            }
        }
        if (v1) {
            float2 rv = *(const float2*)&resid[(size_t)r1 * D + col];
            float2 o;
            o.x = fmaxf(acc[nt][2] + rv.x, 0.f);
            o.y = fmaxf(acc[nt][3] + rv.y, 0.f);
            *(float2*)&out[(size_t)r1 * D + col] = o;
            if (WRITE_Y) {
                float2 yv = make_float2(o.x * di1, o.y * di1);
                *(float2*)&g_y[g][(size_t)r1 * D + col] = yv;
            }
        }
    }
}

// gather seed rows
__global__ void k_seed(const int* __restrict__ s0, const int* __restrict__ s1,
                       const float* __restrict__ ent0, const float* __restrict__ ent1,
                       float* __restrict__ o0, float* __restrict__ o1, int nseed) {
    int w = (blockIdx.x * blockDim.x + threadIdx.x) >> 5;
    if (w >= 2 * nseed) return;
    int lane = threadIdx.x & 31;
    int which = (w >= nseed) ? 1 : 0;
    int k = w - which * nseed;
    const int* s = which ? s1 : s0;
    const float4* ent = (const float4*)(which ? ent1 : ent0);
    float4* o = (float4*)(which ? o1 : o0);
    int r = s[k];
    o[k * 32 + lane] = ent[r * 32 + lane];
}

// ---------------- host launcher ----------------
extern "C" void kernel_launch(void* const* d_in, const int* in_sizes, int n_in,
                              void* d_out, int out_size) {
    const int n = in_sizes[4] / D;
    const int E = in_sizes[6] / 2;
    const int nseed = in_sizes[0];

    const int* seeds[2] = {(const int*)d_in[0], (const int*)d_in[1]};
    const float* emb[2] = {(const float*)d_in[4], (const float*)d_in[5]};
    const int2* edges[2] = {(const int2*)d_in[6], (const int2*)d_in[7]};
    const float* W1 = (const float*)d_in[8];
    const float* W2 = (const float*)d_in[9];

    float* out = (float*)d_out;
    float* out_seed[2] = {out, out + (size_t)nseed * D};
    float* out_ent[2] = {out + (size_t)2 * nseed * D,
                         out + (size_t)2 * nseed * D + (size_t)n * D};

    static cudaStream_t s_aux = [] {
        cudaStream_t s;
        cudaStreamCreateWithFlags(&s, cudaStreamNonBlocking);
        return s;
    }();
    static cudaEvent_t ev_fork = [] {
        cudaEvent_t e;
        cudaEventCreateWithFlags(&e, cudaEventDisableTiming);
        return e;
    }();
    static cudaEvent_t ev_join = [] {
        cudaEvent_t e;
        cudaEventCreateWithFlags(&e, cudaEventDisableTiming);
        return e;
    }();
    static bool attr_done = [] {
        cudaFuncSetAttribute(k_hgemm<true>, cudaFuncAttributeMaxDynamicSharedMemorySize, SMEM_HG);
        cudaFuncSetAttribute(k_hgemm<false>, cudaFuncAttributeMaxDynamicSharedMemorySize, SMEM_HG);
        return true;
    }();
    (void)attr_done;

    const int nb_scan = (n + 1023) / 1024;
    const int agg_grid = (n * 32 + 255) / 256;
    const int hg_grid = (n + 127) / 128;

    // W split (shared by both graphs) before the fork
    k_prepw<<<64, 256>>>(W1, 0);
    k_prepw<<<64, 256>>>(W2, 1);

    cudaEventRecord(ev_fork, 0);
    cudaStreamWaitEvent(s_aux, ev_fork, 0);

    cudaStream_t strm[2] = {0, s_aux};
    for (int g = 0; g < 2; g++) {
        cudaStream_t s = strm[g];
        k_zero_cnt<<<(n + 255) / 256, 256, 0, s>>>(n, g);
        k_count<<<(E + 255) / 256, 256, 0, s>>>(edges[g], E, g);
        k_scan1<<<nb_scan, 1024, 0, s>>>(n, g);
        k_scan2<<<1, 256, 0, s>>>(nb_scan, g);
        k_scan3<<<nb_scan, 1024, 0, s>>>(n, g);
        k_build<<<(E + 255) / 256, 256, 0, s>>>(edges[g], E, g);
        k_init<<<(n * 32 + 255) / 256, 256, 0, s>>>(emb[g], n, g);
        // layer 1
        k_agg<<<agg_grid, 256, 0, s>>>(n, g);
        k_hgemm<true><<<hg_grid, 256, SMEM_HG, s>>>(g, 0, emb[g], nullptr, n);
        // layer 2
        k_agg<<<agg_grid, 256, 0, s>>>(n, g);
        k_hgemm<false><<<hg_grid, 256, SMEM_HG, s>>>(g, 1, nullptr, out_ent[g], n);
    }

    cudaEventRecord(ev_join, s_aux);
    cudaStreamWaitEvent(0, ev_join, 0);
    k_seed<<<(2 * nseed * 32 + 255) / 256, 256>>>(seeds[0], seeds[1], out_ent[0], out_ent[1],
                                                  out_seed[0], out_seed[1], nseed);
}